// round 1
// baseline (speedup 1.0000x reference)
#include <cuda_runtime.h>

#define N_ROWS 16384
#define DDIM   2048
#define KCODES 1024

#define BN 64
#define BK 128
#define BD 16

__device__ float g_enorm[KCODES];   // 0.5 * ||e_k||^2
__device__ int   g_best[N_ROWS];

// ---------------------------------------------------------------------------
// Kernel 1: per-code half squared norm
// ---------------------------------------------------------------------------
__global__ void enorm_kernel(const float* __restrict__ e) {
    int k = blockIdx.x;
    const float4* row = reinterpret_cast<const float4*>(e + (size_t)k * DDIM);
    float s = 0.f;
    for (int i = threadIdx.x; i < DDIM / 4; i += blockDim.x) {
        float4 v = row[i];
        s += v.x * v.x + v.y * v.y + v.z * v.z + v.w * v.w;
    }
#pragma unroll
    for (int o = 16; o; o >>= 1) s += __shfl_xor_sync(0xffffffffu, s, o);
    __shared__ float ss[8];
    if ((threadIdx.x & 31) == 0) ss[threadIdx.x >> 5] = s;
    __syncthreads();
    if (threadIdx.x == 0) {
        float t = 0.f;
        for (int i = 0; i < (int)blockDim.x / 32; i++) t += ss[i];
        g_enorm[k] = 0.5f * t;
    }
}

// ---------------------------------------------------------------------------
// Kernel 2: fused score GEMM + argmax.
//   score[n][k] = x_n . e_k - 0.5*||e_k||^2 ; g_best[n] = argmax_k score
// Tiling: BN=64 rows x BK=128 codes x BD=16, 256 threads (16x16),
// each thread owns a 4x8 microtile.
// ---------------------------------------------------------------------------
__global__ __launch_bounds__(256, 2)
void score_argmax_kernel(const float* __restrict__ x,
                         const float* __restrict__ e) {
    __shared__ float As[BD][BN];     // As[d][row]
    __shared__ float Bs[BD][BK];     // Bs[d][col]

    const int tid = threadIdx.x;
    const int tx = tid & 15;         // column-group 0..15  (8 cols each)
    const int ty = tid >> 4;         // row-group    0..15  (4 rows each)
    const int block_row = blockIdx.x * BN;

    // load indices for the tile-fill phase
    const int lrow = tid >> 2;           // 0..63
    const int ld0  = (tid & 3) * 4;      // 0,4,8,12

    float best_val[4];
    int   best_idx[4];
#pragma unroll
    for (int i = 0; i < 4; i++) { best_val[i] = -3.4e38f; best_idx[i] = 0; }

    for (int k0 = 0; k0 < KCODES; k0 += BK) {
        float acc[4][8];
#pragma unroll
        for (int i = 0; i < 4; i++)
#pragma unroll
            for (int j = 0; j < 8; j++) acc[i][j] = 0.f;

        for (int d0 = 0; d0 < DDIM; d0 += BD) {
            __syncthreads();
            // fill A tile: 64 rows x 16 d  (one float4 per thread)
            {
                float4 v = *reinterpret_cast<const float4*>(
                    x + (size_t)(block_row + lrow) * DDIM + d0 + ld0);
                As[ld0 + 0][lrow] = v.x;
                As[ld0 + 1][lrow] = v.y;
                As[ld0 + 2][lrow] = v.z;
                As[ld0 + 3][lrow] = v.w;
            }
            // fill B tile: 128 codes x 16 d (two float4 per thread)
#pragma unroll
            for (int rep = 0; rep < 2; rep++) {
                int col = lrow + rep * 64;
                float4 v = *reinterpret_cast<const float4*>(
                    e + (size_t)(k0 + col) * DDIM + d0 + ld0);
                Bs[ld0 + 0][col] = v.x;
                Bs[ld0 + 1][col] = v.y;
                Bs[ld0 + 2][col] = v.z;
                Bs[ld0 + 3][col] = v.w;
            }
            __syncthreads();

#pragma unroll
            for (int d = 0; d < BD; d++) {
                float4 a  = *reinterpret_cast<const float4*>(&As[d][ty * 4]);
                float4 b0 = *reinterpret_cast<const float4*>(&Bs[d][tx * 8]);
                float4 b1 = *reinterpret_cast<const float4*>(&Bs[d][tx * 8 + 4]);
                float av[4] = {a.x, a.y, a.z, a.w};
                float bv[8] = {b0.x, b0.y, b0.z, b0.w, b1.x, b1.y, b1.z, b1.w};
#pragma unroll
                for (int i = 0; i < 4; i++)
#pragma unroll
                    for (int j = 0; j < 8; j++)
                        acc[i][j] = fmaf(av[i], bv[j], acc[i][j]);
            }
        }

        // epilogue: subtract 0.5*||e||^2, argmax over this chunk
        float en[8];
#pragma unroll
        for (int j = 0; j < 8; j++) en[j] = g_enorm[k0 + tx * 8 + j];

#pragma unroll
        for (int i = 0; i < 4; i++) {
            float bv = -3.4e38f;
            int   bi = 0x7fffffff;
#pragma unroll
            for (int j = 0; j < 8; j++) {
                float s = acc[i][j] - en[j];
                if (s > bv) { bv = s; bi = k0 + tx * 8 + j; }
            }
            // reduce across the 16 column-group lanes (xor offsets < 16 stay
            // inside the 16-lane group)
#pragma unroll
            for (int o = 8; o; o >>= 1) {
                float ov = __shfl_xor_sync(0xffffffffu, bv, o);
                int   oi = __shfl_xor_sync(0xffffffffu, bi, o);
                if (ov > bv || (ov == bv && oi < bi)) { bv = ov; bi = oi; }
            }
            if (bv > best_val[i] || (bv == best_val[i] && bi < best_idx[i])) {
                best_val[i] = bv; best_idx[i] = bi;
            }
        }
    }

    if (tx == 0) {
#pragma unroll
        for (int i = 0; i < 4; i++)
            g_best[block_row + ty * 4 + i] = best_idx[i];
    }
}

// ---------------------------------------------------------------------------
// Kernel 3: gather codebook rows into the output
// ---------------------------------------------------------------------------
__global__ void gather_kernel(const float* __restrict__ e,
                              float* __restrict__ out) {
    int n = blockIdx.x;
    int best = g_best[n];
    const float4* src = reinterpret_cast<const float4*>(e + (size_t)best * DDIM);
    float4* dst = reinterpret_cast<float4*>(out + (size_t)n * DDIM);
#pragma unroll
    for (int r = 0; r < 2; r++)
        dst[threadIdx.x + r * 256] = src[threadIdx.x + r * 256];
}

// Kernel 4: optional tail — indices (as float) appended after quantize
__global__ void tail_kernel(float* __restrict__ out, int extra) {
    for (int i = blockIdx.x * blockDim.x + threadIdx.x; i < extra;
         i += gridDim.x * blockDim.x) {
        int n = (i < N_ROWS) ? i : (N_ROWS - 1);
        out[(size_t)N_ROWS * DDIM + i] = (float)g_best[n];
    }
}

extern "C" void kernel_launch(void* const* d_in, const int* in_sizes, int n_in,
                              void* d_out, int out_size) {
    const float* x = (const float*)d_in[0];   // [4,4096,2048] fp32
    const float* e = (const float*)d_in[1];   // [1024,2048]  fp32
    float* out = (float*)d_out;

    enorm_kernel<<<KCODES, 256>>>(e);
    score_argmax_kernel<<<N_ROWS / BN, 256>>>(x, e);
    gather_kernel<<<N_ROWS, 256>>>(e, out);

    int extra = out_size - N_ROWS * DDIM;
    if (extra > 0) {
        int blocks = (extra + 255) / 256;
        if (blocks > 148) blocks = 148;
        tail_kernel<<<blocks, 256>>>(out, extra);
    }
}

// round 3
// speedup vs baseline: 2.0858x; 2.0858x over previous
#include <cuda_runtime.h>
#include <cuda_bf16.h>
#include <cstdint>

#define N_ROWS 16384
#define DDIM   2048
#define KCODES 1024

#define M_TILE 128        // rows per CTA
#define NCH    128        // codes per chunk
#define NCHUNK (KCODES / NCH)     // 8
#define KT     32         // fp32 K elements per stage
#define NSTEP  (DDIM / KT)        // 64

__device__ float g_enorm[KCODES];
__device__ int   g_best[N_ROWS];

// ---------------------------------------------------------------------------
// smem layout (dynamic):
//   [0, 1024)        u64 best[128]
//   [1024, 5120)     float enorm[1024]
//   [5120, ...)      2 stages; stage = {A[3][128][80B], B[3][128][80B]}
// row stride 80B (40 bf16, 32 used): stride-80 mod 128 is conflict-free for
// both STS.128 and ldmatrix.
// ---------------------------------------------------------------------------
#define ROWB      80
#define VERB      (128 * ROWB)       // 10240 per version
#define HALF_ST   (3 * VERB)         // 30720 (A block or B block)
#define STAGE_SZ  (2 * HALF_ST)      // 61440
#define SM_BEST   0
#define SM_ENORM  1024
#define SM_STAGE  5120
#define SMEM_TOTAL (SM_STAGE + 2 * STAGE_SZ)   // 128000

static __device__ __forceinline__ uint32_t smem_u32(const void* p) {
    uint32_t a;
    asm("{ .reg .u64 t; cvta.to.shared.u64 t, %1; cvt.u32.u64 %0, t; }"
        : "=r"(a) : "l"(p));
    return a;
}

#define LDSM_X4(r, addr)                                                     \
    asm volatile("ldmatrix.sync.aligned.m8n8.x4.shared.b16 {%0,%1,%2,%3}, [%4];" \
        : "=r"((r)[0]), "=r"((r)[1]), "=r"((r)[2]), "=r"((r)[3]) : "r"(addr))

#define MMA_BF16(d, a, b0, b1)                                               \
    asm volatile("mma.sync.aligned.m16n8k16.row.col.f32.bf16.bf16.f32 "      \
        "{%0,%1,%2,%3}, {%4,%5,%6,%7}, {%8,%9}, {%0,%1,%2,%3};"              \
        : "+f"((d)[0]), "+f"((d)[1]), "+f"((d)[2]), "+f"((d)[3])             \
        : "r"((a)[0]), "r"((a)[1]), "r"((a)[2]), "r"((a)[3]),                \
          "r"(b0), "r"(b1))

static __device__ __forceinline__ float bfr(float f) {
    return __bfloat162float(__float2bfloat16_rn(f));
}
static __device__ __forceinline__ uint32_t packbf(float a, float b) {
    __nv_bfloat162 t = __floats2bfloat162_rn(a, b);
    uint32_t u; memcpy(&u, &t, 4); return u;
}
static __device__ __forceinline__ uint32_t encf(float f) {
    uint32_t u = __float_as_uint(f);
    return (u & 0x80000000u) ? ~u : (u | 0x80000000u);
}

// ---------------------------------------------------------------------------
__global__ void enorm_kernel(const float* __restrict__ e) {
    int k = blockIdx.x;
    const float4* row = reinterpret_cast<const float4*>(e + (size_t)k * DDIM);
    float s = 0.f;
    for (int i = threadIdx.x; i < DDIM / 4; i += blockDim.x) {
        float4 v = row[i];
        s += v.x * v.x + v.y * v.y + v.z * v.z + v.w * v.w;
    }
#pragma unroll
    for (int o = 16; o; o >>= 1) s += __shfl_xor_sync(0xffffffffu, s, o);
    __shared__ float ss[8];
    if ((threadIdx.x & 31) == 0) ss[threadIdx.x >> 5] = s;
    __syncthreads();
    if (threadIdx.x == 0) {
        float t = 0.f;
        for (int i = 0; i < (int)blockDim.x / 32; i++) t += ss[i];
        g_enorm[k] = 0.5f * t;
    }
}

// ---------------------------------------------------------------------------
// score + argmax: bf16x3 (6-product) emulated-fp32 GEMM on mma.sync HMMA.
// ---------------------------------------------------------------------------
__global__ __launch_bounds__(256)
void score_argmax_mma(const float* __restrict__ x, const float* __restrict__ e) {
    extern __shared__ char smem[];
    const uint32_t sbase = smem_u32(smem);
    unsigned long long* best = reinterpret_cast<unsigned long long*>(smem + SM_BEST);
    float* esm = reinterpret_cast<float*>(smem + SM_ENORM);

    const int tid  = threadIdx.x;
    const int lane = tid & 31;
    const int wid  = tid >> 5;
    const int wm   = wid & 3;          // warp row group (4)
    const int wn   = wid >> 2;         // warp col group (2)
    const int brow = blockIdx.x * M_TILE;

    if (tid < 128) best[tid] = 0ull;
    for (int i = tid; i < KCODES; i += 256) esm[i] = g_enorm[i];

    // fill-phase mapping: row = tid&127, quads {qb, qb+2}, qb = tid>>7
    const int frow = tid & 127;
    const int qb   = tid >> 7;

    float4 rA[2][2], rB[2][2];

    // prefetch (c=0, kt=0)
    {
        const float* xp = x + (size_t)(brow + frow) * DDIM;
        const float* ep = e + (size_t)frow * DDIM;
#pragma unroll
        for (int i = 0; i < 2; i++) {
            int off = (qb + 2 * i) * 8;
            rA[i][0] = *reinterpret_cast<const float4*>(xp + off);
            rA[i][1] = *reinterpret_cast<const float4*>(xp + off + 4);
            rB[i][0] = *reinterpret_cast<const float4*>(ep + off);
            rB[i][1] = *reinterpret_cast<const float4*>(ep + off + 4);
        }
    }

    // convert + store helper (macro-ish via lambda)
    auto convert_sts = [&](int stage) {
        char* st = smem + SM_STAGE + stage * STAGE_SZ;
#pragma unroll
        for (int half = 0; half < 2; half++) {         // 0 = A, 1 = B
            float4 (*rr)[2] = half ? rB : rA;
            char* base = st + half * HALF_ST;
#pragma unroll
            for (int i = 0; i < 2; i++) {
                float f[8] = {rr[i][0].x, rr[i][0].y, rr[i][0].z, rr[i][0].w,
                              rr[i][1].x, rr[i][1].y, rr[i][1].z, rr[i][1].w};
                uint4 H, M, L;
                uint32_t* hw = reinterpret_cast<uint32_t*>(&H);
                uint32_t* mw = reinterpret_cast<uint32_t*>(&M);
                uint32_t* lw = reinterpret_cast<uint32_t*>(&L);
#pragma unroll
                for (int j = 0; j < 4; j++) {
                    float a = f[2 * j], b = f[2 * j + 1];
                    float ha = bfr(a), hb = bfr(b);
                    float ra = a - ha, rb = b - hb;
                    float ma = bfr(ra), mb = bfr(rb);
                    float la = ra - ma, lb = rb - mb;
                    hw[j] = packbf(ha, hb);
                    mw[j] = packbf(ma, mb);
                    lw[j] = packbf(la, lb);
                }
                int q = qb + 2 * i;
                char* p = base + frow * ROWB + q * 16;
                *reinterpret_cast<uint4*>(p)            = H;
                *reinterpret_cast<uint4*>(p + VERB)     = M;
                *reinterpret_cast<uint4*>(p + 2 * VERB) = L;
            }
        }
    };

    convert_sts(0);
    __syncthreads();

    // ldmatrix address components
    const uint32_t aRowOff = (uint32_t)(wm * 32 + (lane & 15)) * ROWB +
                             ((lane >> 4) << 4);
    const uint32_t bRowOff = (uint32_t)(wn * 64 + ((lane >> 4) << 3) + (lane & 7)) * ROWB +
                             (((lane >> 3) & 1) << 4);

    int stage = 0;
    for (int c = 0; c < NCHUNK; c++) {
        float acc[2][8][4];
#pragma unroll
        for (int mi = 0; mi < 2; mi++)
#pragma unroll
            for (int ni = 0; ni < 8; ni++)
#pragma unroll
                for (int k = 0; k < 4; k++) acc[mi][ni][k] = 0.f;

        for (int kt = 0; kt < NSTEP; kt++) {
            int nc = c, nk = kt + 1;
            if (nk == NSTEP) { nk = 0; nc++; }
            const bool have_next = (nc < NCHUNK);

            if (have_next) {
                const float* xp = x + (size_t)(brow + frow) * DDIM + nk * KT;
                const float* ep = e + (size_t)(nc * NCH + frow) * DDIM + nk * KT;
#pragma unroll
                for (int i = 0; i < 2; i++) {
                    int off = (qb + 2 * i) * 8;
                    rA[i][0] = *reinterpret_cast<const float4*>(xp + off);
                    rA[i][1] = *reinterpret_cast<const float4*>(xp + off + 4);
                    rB[i][0] = *reinterpret_cast<const float4*>(ep + off);
                    rB[i][1] = *reinterpret_cast<const float4*>(ep + off + 4);
                }
            }

            // MMA on current stage
            const uint32_t aB = sbase + SM_STAGE + stage * STAGE_SZ;
            const uint32_t bB = aB + HALF_ST;
#pragma unroll
            for (int kq = 0; kq < 2; kq++) {
                uint32_t aF[3][2][4];
#pragma unroll
                for (int v = 0; v < 3; v++)
#pragma unroll
                    for (int mi = 0; mi < 2; mi++)
                        LDSM_X4(aF[v][mi],
                                aB + v * VERB + aRowOff + mi * 16 * ROWB + kq * 32);
                uint32_t bF[3][4][4];
#pragma unroll
                for (int v = 0; v < 3; v++)
#pragma unroll
                    for (int nj = 0; nj < 4; nj++)
                        LDSM_X4(bF[v][nj],
                                bB + v * VERB + bRowOff + nj * 16 * ROWB + kq * 32);

                // 6 products: hh, hm, mh, hl, lh, mm
                const int pa[6] = {0, 0, 1, 0, 2, 1};
                const int pb[6] = {0, 1, 0, 2, 0, 1};
#pragma unroll
                for (int p = 0; p < 6; p++) {
#pragma unroll
                    for (int mi = 0; mi < 2; mi++)
#pragma unroll
                        for (int ni = 0; ni < 8; ni++)
                            MMA_BF16(acc[mi][ni], aF[pa[p]][mi],
                                     bF[pb[p]][ni >> 1][(ni & 1) * 2],
                                     bF[pb[p]][ni >> 1][(ni & 1) * 2 + 1]);
                }
            }

            if (have_next) convert_sts(stage ^ 1);
            __syncthreads();
            stage ^= 1;
        }

        // epilogue: fused argmax for this 128-code chunk
#pragma unroll
        for (int mi = 0; mi < 2; mi++)
#pragma unroll
            for (int half = 0; half < 2; half++) {
                float bv = -3.4e38f;
                int   bi = 0;
#pragma unroll
                for (int ni = 0; ni < 8; ni++)
#pragma unroll
                    for (int ee = 0; ee < 2; ee++) {
                        int code = c * NCH + wn * 64 + ni * 8 + (lane & 3) * 2 + ee;
                        float s = acc[mi][ni][half * 2 + ee] - esm[code];
                        if (s > bv || (s == bv && code < bi)) { bv = s; bi = code; }
                    }
#pragma unroll
                for (int o = 1; o <= 2; o <<= 1) {
                    float ov = __shfl_xor_sync(0xffffffffu, bv, o);
                    int   oi = __shfl_xor_sync(0xffffffffu, bi, o);
                    if (ov > bv || (ov == bv && oi < bi)) { bv = ov; bi = oi; }
                }
                if ((lane & 3) == 0) {
                    int row = wm * 32 + mi * 16 + (lane >> 2) + half * 8;
                    unsigned long long key =
                        ((unsigned long long)encf(bv) << 32) |
                        (uint32_t)(0x7fffffff - bi);
                    atomicMax(&best[row], key);
                }
            }
    }

    __syncthreads();
    if (tid < 128) {
        unsigned long long key = best[tid];
        g_best[brow + tid] = 0x7fffffff - (int)(uint32_t)(key & 0xffffffffu);
    }
}

// ---------------------------------------------------------------------------
__global__ void gather_kernel(const float* __restrict__ e,
                              float* __restrict__ out) {
    int n = blockIdx.x;
    int best = g_best[n];
    const float4* src = reinterpret_cast<const float4*>(e + (size_t)best * DDIM);
    float4* dst = reinterpret_cast<float4*>(out + (size_t)n * DDIM);
#pragma unroll
    for (int r = 0; r < 2; r++)
        dst[threadIdx.x + r * 256] = src[threadIdx.x + r * 256];
}

__global__ void tail_kernel(float* __restrict__ out, int extra) {
    for (int i = blockIdx.x * blockDim.x + threadIdx.x; i < extra;
         i += gridDim.x * blockDim.x) {
        int n = (i < N_ROWS) ? i : (N_ROWS - 1);
        out[(size_t)N_ROWS * DDIM + i] = (float)g_best[n];
    }
}

extern "C" void kernel_launch(void* const* d_in, const int* in_sizes, int n_in,
                              void* d_out, int out_size) {
    const float* x = (const float*)d_in[0];
    const float* e = (const float*)d_in[1];
    float* out = (float*)d_out;

    cudaFuncSetAttribute(score_argmax_mma,
                         cudaFuncAttributeMaxDynamicSharedMemorySize, SMEM_TOTAL);

    enorm_kernel<<<KCODES, 256>>>(e);
    score_argmax_mma<<<N_ROWS / M_TILE, 256, SMEM_TOTAL>>>(x, e);
    gather_kernel<<<N_ROWS, 256>>>(e, out);

    int extra = out_size - N_ROWS * DDIM;
    if (extra > 0) {
        int blocks = (extra + 255) / 256;
        if (blocks > 148) blocks = 148;
        tail_kernel<<<blocks, 256>>>(out, extra);
    }
}

// round 4
// speedup vs baseline: 7.9441x; 3.8086x over previous
#include <cuda_runtime.h>
#include <cuda_bf16.h>
#include <cstdint>

#define N_ROWS 16384
#define DDIM   2048
#define KCODES 1024

__device__ float g_enorm[KCODES];
__device__ int   g_best[N_ROWS];
__device__ float g_scores[(size_t)N_ROWS * KCODES];     // raw bf16 dots (fp32 acc)
__device__ __nv_bfloat16 g_xb[(size_t)N_ROWS * DDIM];
__device__ __nv_bfloat16 g_eb[(size_t)KCODES * DDIM];

// ---------------------------------------------------------------------------
#define ROWB   80                 // 64B payload + pad: 5*16B, ldmatrix conflict-free
#define STG    (256 * ROWB)       // stage: A 128 rows + B 128 rows = 20480 B
#define SMEM_P1 (4 * STG)         // 81920

static __device__ __forceinline__ uint32_t smem_u32(const void* p) {
    uint32_t a;
    asm("{ .reg .u64 t; cvta.to.shared.u64 t, %1; cvt.u32.u64 %0, t; }"
        : "=r"(a) : "l"(p));
    return a;
}

#define LDSM_X4(r, addr)                                                     \
    asm volatile("ldmatrix.sync.aligned.m8n8.x4.shared.b16 {%0,%1,%2,%3}, [%4];" \
        : "=r"((r)[0]), "=r"((r)[1]), "=r"((r)[2]), "=r"((r)[3]) : "r"(addr))

#define MMA_BF16(d, a, b0, b1)                                               \
    asm volatile("mma.sync.aligned.m16n8k16.row.col.f32.bf16.bf16.f32 "      \
        "{%0,%1,%2,%3}, {%4,%5,%6,%7}, {%8,%9}, {%0,%1,%2,%3};"              \
        : "+f"((d)[0]), "+f"((d)[1]), "+f"((d)[2]), "+f"((d)[3])             \
        : "r"((a)[0]), "r"((a)[1]), "r"((a)[2]), "r"((a)[3]),                \
          "r"(b0), "r"(b1))

#define CP16(dst, src)                                                       \
    asm volatile("cp.async.ca.shared.global [%0], [%1], 16;"                 \
                 :: "r"(dst), "l"(src))
#define CP_COMMIT() asm volatile("cp.async.commit_group;" ::: "memory")
#define CP_WAIT2()  asm volatile("cp.async.wait_group 2;" ::: "memory")

// ---------------------------------------------------------------------------
// convert fp32 -> bf16 (packed)
// ---------------------------------------------------------------------------
__global__ void convert_kernel(const float* __restrict__ src,
                               __nv_bfloat16* __restrict__ dst, int n4) {
    for (int i = blockIdx.x * blockDim.x + threadIdx.x; i < n4;
         i += gridDim.x * blockDim.x) {
        float4 v = reinterpret_cast<const float4*>(src)[i];
        __nv_bfloat162 a = __floats2bfloat162_rn(v.x, v.y);
        __nv_bfloat162 b = __floats2bfloat162_rn(v.z, v.w);
        uint2 u; memcpy(&u.x, &a, 4); memcpy(&u.y, &b, 4);
        reinterpret_cast<uint2*>(dst)[i] = u;
    }
}

// ---------------------------------------------------------------------------
__global__ void enorm_kernel(const float* __restrict__ e) {
    int k = blockIdx.x;
    const float4* row = reinterpret_cast<const float4*>(e + (size_t)k * DDIM);
    float s = 0.f;
    for (int i = threadIdx.x; i < DDIM / 4; i += blockDim.x) {
        float4 v = row[i];
        s += v.x * v.x + v.y * v.y + v.z * v.z + v.w * v.w;
    }
#pragma unroll
    for (int o = 16; o; o >>= 1) s += __shfl_xor_sync(0xffffffffu, s, o);
    __shared__ float ss[8];
    if ((threadIdx.x & 31) == 0) ss[threadIdx.x >> 5] = s;
    __syncthreads();
    if (threadIdx.x == 0) {
        float t = 0.f;
        for (int i = 0; i < (int)blockDim.x / 32; i++) t += ss[i];
        g_enorm[k] = 0.5f * t;
    }
}

// ---------------------------------------------------------------------------
// Pass 1: bf16 HMMA GEMM, 128 rows x 128 codes per CTA, KT=32 per stage,
// 4-stage cp.async pipeline. Stores raw dots to g_scores.
// ---------------------------------------------------------------------------
__global__ __launch_bounds__(256, 2)
void pass1_gemm(void) {
    extern __shared__ char smem[];
    const uint32_t sbase = smem_u32(smem);

    const int tid  = threadIdx.x;
    const int lane = tid & 31;
    const int wid  = tid >> 5;
    const int wm   = wid & 3;            // 4 M-groups (32 rows each)
    const int wn   = wid >> 2;           // 2 N-groups (64 codes each)
    const int brow  = blockIdx.y * 128;
    const int bcode = blockIdx.x * 128;

    const __nv_bfloat16* xb = g_xb;
    const __nv_bfloat16* eb = g_eb;

    float acc[2][8][4];
#pragma unroll
    for (int mi = 0; mi < 2; mi++)
#pragma unroll
        for (int ni = 0; ni < 8; ni++)
#pragma unroll
            for (int k = 0; k < 4; k++) acc[mi][ni][k] = 0.f;

    // stage issue: g in [0, 64)
    auto issue = [&](int g) {
        if (g < 64) {
            const int d0 = g * 32;
            const uint32_t st = sbase + (g & 3) * STG;
#pragma unroll
            for (int r = 0; r < 4; r++) {
                int idx = tid + r * 256;         // 0..1023
                int c   = idx & 3;
                if (idx < 512) {
                    int row = idx >> 2;
                    const __nv_bfloat16* src =
                        xb + (size_t)(brow + row) * DDIM + d0 + c * 8;
                    CP16(st + row * ROWB + c * 16, src);
                } else {
                    int row = (idx - 512) >> 2;
                    const __nv_bfloat16* src =
                        eb + (size_t)(bcode + row) * DDIM + d0 + c * 8;
                    CP16(st + 128 * ROWB + row * ROWB + c * 16, src);
                }
            }
        }
        CP_COMMIT();
    };

    issue(0); issue(1); issue(2);

    const uint32_t aRowOff = (uint32_t)(wm * 32 + (lane & 15)) * ROWB +
                             ((lane >> 4) << 4);
    const uint32_t bRowOff = (uint32_t)(wn * 64 + ((lane >> 4) << 3) + (lane & 7)) * ROWB +
                             (((lane >> 3) & 1) << 4);

    for (int kt = 0; kt < 64; kt++) {
        CP_WAIT2();
        __syncthreads();
        issue(kt + 3);

        const uint32_t aB = sbase + (kt & 3) * STG;
        const uint32_t bB = aB + 128 * ROWB;
#pragma unroll
        for (int kq = 0; kq < 2; kq++) {
            uint32_t aF[2][4];
#pragma unroll
            for (int mi = 0; mi < 2; mi++)
                LDSM_X4(aF[mi], aB + aRowOff + mi * 16 * ROWB + kq * 32);
#pragma unroll
            for (int nj = 0; nj < 4; nj++) {
                uint32_t bF[4];
                LDSM_X4(bF, bB + bRowOff + nj * 16 * ROWB + kq * 32);
#pragma unroll
                for (int mi = 0; mi < 2; mi++) {
                    MMA_BF16(acc[mi][nj * 2 + 0], aF[mi], bF[0], bF[1]);
                    MMA_BF16(acc[mi][nj * 2 + 1], aF[mi], bF[2], bF[3]);
                }
            }
        }
    }

    // epilogue: store raw dots
#pragma unroll
    for (int mi = 0; mi < 2; mi++)
#pragma unroll
        for (int half = 0; half < 2; half++) {
            int row = brow + wm * 32 + mi * 16 + (lane >> 2) + half * 8;
#pragma unroll
            for (int ni = 0; ni < 8; ni++) {
                int code = bcode + wn * 64 + ni * 8 + (lane & 3) * 2;
                float2 v = make_float2(acc[mi][ni][half * 2 + 0],
                                       acc[mi][ni][half * 2 + 1]);
                *reinterpret_cast<float2*>(&g_scores[(size_t)row * KCODES + code]) = v;
            }
        }
}

// ---------------------------------------------------------------------------
// Pass 2: per row, max of (dot_bf16 - enorm), rescore candidates within
// MARGIN exactly in fp32, write argmax index.
// ---------------------------------------------------------------------------
#define MARGIN 4.0f

__global__ __launch_bounds__(256)
void pass2_rescue(const float* __restrict__ x, const float* __restrict__ e) {
    const int lane = threadIdx.x & 31;
    const int row  = blockIdx.x * 8 + (threadIdx.x >> 5);

    // adjusted bf16 scores for my 32 codes
    float sc[32];
    float rowmax = -3.4e38f;
    const float* srow = &g_scores[(size_t)row * KCODES];
#pragma unroll
    for (int k = 0; k < 32; k++) {
        sc[k] = srow[k * 32 + lane] - g_enorm[k * 32 + lane];
        rowmax = fmaxf(rowmax, sc[k]);
    }
#pragma unroll
    for (int o = 16; o; o >>= 1)
        rowmax = fmaxf(rowmax, __shfl_xor_sync(0xffffffffu, rowmax, o));
    const float thr = rowmax - MARGIN;

    // x row in registers
    float xr[64];
    const float* xrow = x + (size_t)row * DDIM;
#pragma unroll
    for (int j = 0; j < 64; j++) xr[j] = xrow[j * 32 + lane];

    float bestS = -3.4e38f;
    int   bestI = 0;
#pragma unroll 1
    for (int k = 0; k < 32; k++) {
        unsigned m = __ballot_sync(0xffffffffu, sc[k] >= thr);
        while (m) {
            int l = __ffs(m) - 1;
            m &= m - 1;
            int c = k * 32 + l;
            const float* er = e + (size_t)c * DDIM;
            float p = 0.f;
#pragma unroll
            for (int j = 0; j < 64; j++) p = fmaf(xr[j], er[j * 32 + lane], p);
#pragma unroll
            for (int o = 16; o; o >>= 1) p += __shfl_xor_sync(0xffffffffu, p, o);
            float s = p - g_enorm[c];
            if (s > bestS) { bestS = s; bestI = c; }   // ascending c: ties -> lowest
        }
    }
    if (lane == 0) g_best[row] = bestI;
}

// ---------------------------------------------------------------------------
__global__ void gather_kernel(const float* __restrict__ e,
                              float* __restrict__ out) {
    int n = blockIdx.x;
    int best = g_best[n];
    const float4* src = reinterpret_cast<const float4*>(e + (size_t)best * DDIM);
    float4* dst = reinterpret_cast<float4*>(out + (size_t)n * DDIM);
#pragma unroll
    for (int r = 0; r < 2; r++)
        dst[threadIdx.x + r * 256] = src[threadIdx.x + r * 256];
}

__global__ void tail_kernel(float* __restrict__ out, int extra) {
    for (int i = blockIdx.x * blockDim.x + threadIdx.x; i < extra;
         i += gridDim.x * blockDim.x) {
        int n = (i < N_ROWS) ? i : (N_ROWS - 1);
        out[(size_t)N_ROWS * DDIM + i] = (float)g_best[n];
    }
}

// ---------------------------------------------------------------------------
extern "C" void kernel_launch(void* const* d_in, const int* in_sizes, int n_in,
                              void* d_out, int out_size) {
    const float* x = (const float*)d_in[0];
    const float* e = (const float*)d_in[1];
    float* out = (float*)d_out;

    static __nv_bfloat16* xb_p = nullptr;
    if (!xb_p) {  // symbol addresses are stable; lookup is host-side only
        cudaGetSymbolAddress((void**)&xb_p, g_xb);
        cudaFuncSetAttribute(pass1_gemm,
                             cudaFuncAttributeMaxDynamicSharedMemorySize, SMEM_P1);
    }
    __nv_bfloat16* eb_p; cudaGetSymbolAddress((void**)&eb_p, g_eb);

    convert_kernel<<<1024, 256>>>(x, xb_p, N_ROWS * DDIM / 4);
    convert_kernel<<<256, 256>>>(e, eb_p, KCODES * DDIM / 4);
    enorm_kernel<<<KCODES, 256>>>(e);

    dim3 g1(KCODES / 128, N_ROWS / 128);   // (8, 128)
    pass1_gemm<<<g1, 256, SMEM_P1>>>();

    pass2_rescue<<<N_ROWS / 8, 256>>>(x, e);
    gather_kernel<<<N_ROWS, 256>>>(e, out);

    int extra = out_size - N_ROWS * DDIM;
    if (extra > 0) {
        int blocks = (extra + 255) / 256;
        if (blocks > 148) blocks = 148;
        tail_kernel<<<blocks, 256>>>(out, extra);
    }
}